// round 2
// baseline (speedup 1.0000x reference)
#include <cuda_runtime.h>

// GATv2 GNN, one CTA per batch element. All intermediates live in SMEM.
// Shapes: B=128, N=16, T=48, M=64, F=128, layers 1-2: H=4,C=32; layer 3: H=1,C=64.

#define RS 132            // SMEM row stride in floats (16B aligned, reduces conflicts)
#define NTHREADS 256
#define NEGV -1000000000.0f

static constexpr int SMEM_FLOATS = 3 * 64 * RS + 64 * 64 * 4 + 64; // X,XL,XR + E + IMP
static constexpr int SMEM_BYTES  = SMEM_FLOATS * 4;                 // 167168 B

__device__ __forceinline__ float lrelu(float v) { return fmaxf(v, 0.2f * v); }

// ---------------------------------------------------------------------------
// xl = x @ Wl, xr = x @ Wr   (x: 64 x 128 in smem, W: 128 x FOUT in gmem)
// 8 warps x 8 rows, lane covers FOUT/32 contiguous columns.
// ---------------------------------------------------------------------------
template <int FOUT>
__device__ void dual_matmul(const float* __restrict__ Wl, const float* __restrict__ Wr,
                            const float* xbuf, float* xlbuf, float* xrbuf)
{
    const int w    = threadIdx.x >> 5;
    const int lane = threadIdx.x & 31;
    constexpr int CPL = FOUT / 32;      // 4 (layers 1-2) or 2 (layer 3)
    const int row0 = w * 8;
    const int colbase = lane * CPL;

    float accL[8][CPL], accR[8][CPL];
#pragma unroll
    for (int r = 0; r < 8; r++)
#pragma unroll
        for (int c = 0; c < CPL; c++) { accL[r][c] = 0.f; accR[r][c] = 0.f; }

#pragma unroll 4
    for (int k = 0; k < 128; k++) {
        float xv[8];
#pragma unroll
        for (int r = 0; r < 8; r++) xv[r] = xbuf[(row0 + r) * RS + k];
        float wl[CPL], wr[CPL];
        if constexpr (CPL == 4) {
            float4 a = *(const float4*)(Wl + k * FOUT + colbase);
            float4 b = *(const float4*)(Wr + k * FOUT + colbase);
            wl[0] = a.x; wl[1] = a.y; wl[2] = a.z; wl[3] = a.w;
            wr[0] = b.x; wr[1] = b.y; wr[2] = b.z; wr[3] = b.w;
        } else {
            float2 a = *(const float2*)(Wl + k * FOUT + colbase);
            float2 b = *(const float2*)(Wr + k * FOUT + colbase);
            wl[0] = a.x; wl[1] = a.y;
            wr[0] = b.x; wr[1] = b.y;
        }
#pragma unroll
        for (int r = 0; r < 8; r++)
#pragma unroll
            for (int c = 0; c < CPL; c++) {
                accL[r][c] = fmaf(xv[r], wl[c], accL[r][c]);
                accR[r][c] = fmaf(xv[r], wr[c], accR[r][c]);
            }
    }
#pragma unroll
    for (int r = 0; r < 8; r++)
#pragma unroll
        for (int c = 0; c < CPL; c++) {
            xlbuf[(row0 + r) * RS + colbase + c] = accL[r][c];
            xrbuf[(row0 + r) * RS + colbase + c] = accR[r][c];
        }
}

// ---------------------------------------------------------------------------
// e[h][i][j] = adj(i,j) ? sum_c lrelu(xl[i,h,c] + xr[j,h,c]) * att[h,c] : NEG
// Thread mapping: j = tid & 63; rest = tid>>6; h = rest % HH; ic = rest / HH.
// ---------------------------------------------------------------------------
template <int HH, int CC>
__device__ void compute_e(const float* xlbuf, const float* xrbuf,
                          const float* __restrict__ att,
                          float* ebuf, const int* imp)
{
    const int t    = threadIdx.x;
    const int j    = t & 63;
    const int rest = t >> 6;
    const int h    = rest % HH;
    const int ic   = rest / HH;
    constexpr int ICNT = 16 * HH;       // i-values per thread (64 or 16)
    const int i0 = ic * ICNT;

    float xr[CC], av[CC];
#pragma unroll
    for (int c = 0; c < CC; c += 4) {
        float4 a = *(const float4*)(xrbuf + j * RS + h * CC + c);
        xr[c] = a.x; xr[c + 1] = a.y; xr[c + 2] = a.z; xr[c + 3] = a.w;
        float4 b = *(const float4*)(att + h * CC + c);
        av[c] = b.x; av[c + 1] = b.y; av[c + 2] = b.z; av[c + 3] = b.w;
    }
    const int impj = imp[j];
    for (int i = i0; i < i0 + ICNT; i++) {
        float s0 = 0.f, s1 = 0.f, s2 = 0.f, s3 = 0.f;
        const float* xlrow = xlbuf + i * RS + h * CC;
#pragma unroll
        for (int c = 0; c < CC; c += 4) {
            float4 xv = *(const float4*)(xlrow + c);
            s0 = fmaf(lrelu(xv.x + xr[c]),     av[c],     s0);
            s1 = fmaf(lrelu(xv.y + xr[c + 1]), av[c + 1], s1);
            s2 = fmaf(lrelu(xv.z + xr[c + 2]), av[c + 2], s2);
            s3 = fmaf(lrelu(xv.w + xr[c + 3]), av[c + 3], s3);
        }
        float s = (s0 + s1) + (s2 + s3);
        bool ok = (i == j) || (impj && imp[i]);
        ebuf[(h * 64 + i) * 64 + j] = ok ? s : NEGV;
    }
}

// softmax over i for each (j,h), in place; e layout [h][i][j]
template <int HH>
__device__ void softmax_e(float* ebuf)
{
    const int t = threadIdx.x;
    if (t < 64 * HH) {
        const int j = t & 63;
        const int h = t >> 6;
        float* base = ebuf + h * 4096 + j;
        float mx = -3.4e38f;
        for (int i = 0; i < 64; i++) mx = fmaxf(mx, base[i * 64]);
        float s = 0.f;
        for (int i = 0; i < 64; i++) {
            float ex = __expf(base[i * 64] - mx);
            base[i * 64] = ex;
            s += ex;
        }
        float inv = 1.f / s;
        for (int i = 0; i < 64; i++) base[i * 64] *= inv;
    }
}

// out[j][f] = sum_i alpha[h][i][j] * xl[i][f] + bias[f]
// thread: j = tid & 63, fchunk = tid >> 6 (FOUT/4 features each; h constant per chunk)
template <int HH, int CC, int FOUT>
__device__ void aggregate(const float* xlbuf, const float* ebuf,
                          const float* __restrict__ bias, float* dst, int dst_stride)
{
    const int t = threadIdx.x;
    const int j = t & 63;
    const int fchunk = t >> 6;
    constexpr int FC = FOUT / 4;        // 32 or 16
    const int f0 = fchunk * FC;
    const int h  = f0 / CC;

    float acc[FC];
#pragma unroll
    for (int c = 0; c < FC; c++) acc[c] = 0.f;

    const float* arow = ebuf + h * 4096 + j;
    for (int i = 0; i < 64; i++) {
        float a = arow[i * 64];
        const float* xlrow = xlbuf + i * RS + f0;
#pragma unroll
        for (int c = 0; c < FC; c += 4) {
            float4 v = *(const float4*)(xlrow + c);
            acc[c]     = fmaf(a, v.x, acc[c]);
            acc[c + 1] = fmaf(a, v.y, acc[c + 1]);
            acc[c + 2] = fmaf(a, v.z, acc[c + 2]);
            acc[c + 3] = fmaf(a, v.w, acc[c + 3]);
        }
    }
#pragma unroll
    for (int c = 0; c < FC; c++)
        dst[j * dst_stride + f0 + c] = acc[c] + bias[f0 + c];
}

// layernorm over 128 features + relu, in place. Warp per row, 8 rows per warp.
__device__ void ln_relu(float* xbuf, const float* __restrict__ g, const float* __restrict__ bb)
{
    const int w    = threadIdx.x >> 5;
    const int lane = threadIdx.x & 31;
    for (int r = w; r < 64; r += 8) {
        float4 v = *(const float4*)(xbuf + r * RS + lane * 4);
        float sum = v.x + v.y + v.z + v.w;
        float sq  = v.x * v.x + v.y * v.y + v.z * v.z + v.w * v.w;
#pragma unroll
        for (int o = 16; o > 0; o >>= 1) {
            sum += __shfl_xor_sync(0xffffffffu, sum, o);
            sq  += __shfl_xor_sync(0xffffffffu, sq, o);
        }
        float mean = sum * (1.f / 128.f);
        float var  = sq * (1.f / 128.f) - mean * mean;
        float rstd = rsqrtf(var + 1e-5f);
        float4 gg = *(const float4*)(g + lane * 4);
        float4 bv = *(const float4*)(bb + lane * 4);
        float4 o;
        o.x = fmaxf((v.x - mean) * rstd * gg.x + bv.x, 0.f);
        o.y = fmaxf((v.y - mean) * rstd * gg.y + bv.y, 0.f);
        o.z = fmaxf((v.z - mean) * rstd * gg.z + bv.z, 0.f);
        o.w = fmaxf((v.w - mean) * rstd * gg.w + bv.w, 0.f);
        *(float4*)(xbuf + r * RS + lane * 4) = o;
    }
}

__global__ void __launch_bounds__(NTHREADS, 1)
GNN_61040075210810_kernel(
    const float* __restrict__ team_obs, const float* __restrict__ target_obs,
    const float* __restrict__ team_mask, const float* __restrict__ ltm,
    const float* __restrict__ W_emb, const float* __restrict__ b_emb,
    const float* __restrict__ Wl1, const float* __restrict__ Wr1,
    const float* __restrict__ att1, const float* __restrict__ b1,
    const float* __restrict__ Wl2, const float* __restrict__ Wr2,
    const float* __restrict__ att2, const float* __restrict__ b2,
    const float* __restrict__ Wl3, const float* __restrict__ Wr3,
    const float* __restrict__ att3, const float* __restrict__ b3,
    const float* __restrict__ ln1g, const float* __restrict__ ln1b,
    const float* __restrict__ ln2g, const float* __restrict__ ln2b,
    float* __restrict__ out)
{
    extern __shared__ float smf[];
    float* X  = smf;
    float* XL = smf + 64 * RS;
    float* XR = smf + 2 * 64 * RS;
    float* E  = smf + 3 * 64 * RS;          // 16384 floats; FIN aliases first 1024
    int*   IMP = (int*)(smf + 3 * 64 * RS + 16384);

    const int b = blockIdx.x;
    const int t = threadIdx.x;

    // ---- feature assembly: fin (64 x 16) into E-alias ----
    float* FIN = E;
    for (int idx = t; idx < 1024; idx += NTHREADS) {
        int m = idx >> 4, k = idx & 15;
        float v;
        if (m < 16) {
            v = (k < 14) ? team_obs[(b * 16 + m) * 14 + k] : 0.f;
        } else {
            int tt = m - 16;
            if (k < 12)      v = target_obs[(b * 48 + tt) * 15 + k];
            else if (k < 14) v = 0.f;
            else             v = target_obs[(b * 48 + tt) * 15 + (k - 2)];
        }
        FIN[idx] = v;
    }
    if (t < 64) {
        bool ok = (t < 16) ? (team_mask[b * 32 + t] != NEGV)
                           : (ltm[b * 49 + (t - 16)] != 0.0f);
        IMP[t] = ok ? 1 : 0;
    }
    __syncthreads();

    // ---- embedding: X = FIN @ W_emb + b_emb  (64x16 @ 16x128) ----
    {
        const int w = t >> 5, lane = t & 31;
        const int row0 = w * 8;
        float acc[8][4];
#pragma unroll
        for (int r = 0; r < 8; r++)
#pragma unroll
            for (int c = 0; c < 4; c++) acc[r][c] = 0.f;
#pragma unroll
        for (int k = 0; k < 16; k++) {
            float xv[8];
#pragma unroll
            for (int r = 0; r < 8; r++) xv[r] = FIN[(row0 + r) * 16 + k];
            float4 wv = *(const float4*)(W_emb + k * 128 + lane * 4);
#pragma unroll
            for (int r = 0; r < 8; r++) {
                acc[r][0] = fmaf(xv[r], wv.x, acc[r][0]);
                acc[r][1] = fmaf(xv[r], wv.y, acc[r][1]);
                acc[r][2] = fmaf(xv[r], wv.z, acc[r][2]);
                acc[r][3] = fmaf(xv[r], wv.w, acc[r][3]);
            }
        }
        float4 be = *(const float4*)(b_emb + lane * 4);
#pragma unroll
        for (int r = 0; r < 8; r++) {
            X[(row0 + r) * RS + lane * 4 + 0] = acc[r][0] + be.x;
            X[(row0 + r) * RS + lane * 4 + 1] = acc[r][1] + be.y;
            X[(row0 + r) * RS + lane * 4 + 2] = acc[r][2] + be.z;
            X[(row0 + r) * RS + lane * 4 + 3] = acc[r][3] + be.w;
        }
    }
    __syncthreads();

    // ---- layer 1 ----
    dual_matmul<128>(Wl1, Wr1, X, XL, XR);
    __syncthreads();
    compute_e<4, 32>(XL, XR, att1, E, IMP);
    __syncthreads();
    softmax_e<4>(E);
    __syncthreads();
    aggregate<4, 32, 128>(XL, E, b1, X, RS);
    __syncthreads();
    ln_relu(X, ln1g, ln1b);
    __syncthreads();

    // ---- layer 2 ----
    dual_matmul<128>(Wl2, Wr2, X, XL, XR);
    __syncthreads();
    compute_e<4, 32>(XL, XR, att2, E, IMP);
    __syncthreads();
    softmax_e<4>(E);
    __syncthreads();
    aggregate<4, 32, 128>(XL, E, b2, X, RS);
    __syncthreads();
    ln_relu(X, ln2g, ln2b);
    __syncthreads();

    // ---- layer 3 (H=1, C=64, FOUT=64) ----
    dual_matmul<64>(Wl3, Wr3, X, XL, XR);
    __syncthreads();
    compute_e<1, 64>(XL, XR, att3, E, IMP);
    __syncthreads();
    softmax_e<1>(E);
    __syncthreads();
    aggregate<1, 64, 64>(XL, E, b3, out + b * 64 * 64, 64);
}

extern "C" void kernel_launch(void* const* d_in, const int* in_sizes, int n_in,
                              void* d_out, int out_size)
{
    (void)in_sizes; (void)n_in; (void)out_size;
    cudaFuncSetAttribute(GNN_61040075210810_kernel,
                         cudaFuncAttributeMaxDynamicSharedMemorySize, SMEM_BYTES);
    GNN_61040075210810_kernel<<<128, NTHREADS, SMEM_BYTES>>>(
        (const float*)d_in[0],  (const float*)d_in[1],
        (const float*)d_in[2],  (const float*)d_in[3],
        (const float*)d_in[4],  (const float*)d_in[5],
        (const float*)d_in[6],  (const float*)d_in[7],
        (const float*)d_in[8],  (const float*)d_in[9],
        (const float*)d_in[10], (const float*)d_in[11],
        (const float*)d_in[12], (const float*)d_in[13],
        (const float*)d_in[14], (const float*)d_in[15],
        (const float*)d_in[16], (const float*)d_in[17],
        (const float*)d_in[18], (const float*)d_in[19],
        (const float*)d_in[20], (const float*)d_in[21],
        (float*)d_out);
}

// round 3
// speedup vs baseline: 1.2164x; 1.2164x over previous
#include <cuda_runtime.h>
#include <cstdint>

// GATv2 GNN, one CTA per batch element, 512 threads. All intermediates in SMEM.
// B=128, M=64, F=128; layers 1-2: H=4,C=32; layer 3: H=1,C=64.

#define RS 132              // row stride (floats) for X/XL/XR
#define NT 512
#define EHS 4112            // e head stride = 64*64 + 16 (breaks h-bank aliasing)
#define NEGV -1000000000.0f

#define OFF_X   0
#define OFF_XL  (64*RS)
#define OFF_XR  (2*64*RS)
#define OFF_E   (3*64*RS)
#define OFF_IMP (OFF_E + 4*EHS)
#define OFF_DL  (OFF_IMP + 64)
#define OFF_DR  (OFF_DL + 256)
#define SMEM_FLOATS (OFF_DR + 256)
#define SMEM_BYTES  (SMEM_FLOATS * 4)   // 169472 B

// ---- packed f32x2 helpers (FFMA2 is PTX-only on sm_103a) ----
__device__ __forceinline__ uint64_t pk2(float lo, float hi) {
    uint64_t d; asm("mov.b64 %0, {%1, %2};" : "=l"(d) : "f"(lo), "f"(hi)); return d;
}
__device__ __forceinline__ float2 upk2(uint64_t v) {
    float lo, hi; asm("mov.b64 {%0, %1}, %2;" : "=f"(lo), "=f"(hi) : "l"(v));
    return make_float2(lo, hi);
}
__device__ __forceinline__ uint64_t fadd2(uint64_t a, uint64_t b) {
    uint64_t d; asm("add.rn.f32x2 %0, %1, %2;" : "=l"(d) : "l"(a), "l"(b)); return d;
}
__device__ __forceinline__ void ffma2(uint64_t& d, uint64_t a, uint64_t b, uint64_t c) {
    asm("fma.rn.f32x2 %0, %1, %2, %3;" : "=l"(d) : "l"(a), "l"(b), "l"(c));
}

// ---------------------------------------------------------------------------
// xl = x @ Wl, xr = x @ Wr. 16 warps x 4 rows, lane covers FOUT/32 columns,
// packed FFMA2 over the column dimension.
// ---------------------------------------------------------------------------
template <int FOUT>
__device__ void dual_matmul(const float* __restrict__ Wl, const float* __restrict__ Wr,
                            const float* xbuf, float* xlbuf, float* xrbuf)
{
    const int w = threadIdx.x >> 5;
    const int lane = threadIdx.x & 31;
    constexpr int CP2 = FOUT / 64;      // packed cols per lane: 2 or 1
    const int row0 = w * 4;
    const int colbase = lane * (FOUT / 32);

    uint64_t accL[4][CP2], accR[4][CP2];
#pragma unroll
    for (int r = 0; r < 4; r++)
#pragma unroll
        for (int c = 0; c < CP2; c++) { accL[r][c] = 0ull; accR[r][c] = 0ull; }

#pragma unroll 4
    for (int k = 0; k < 128; k++) {
        uint64_t xvv[4];
#pragma unroll
        for (int r = 0; r < 4; r++) {
            float xv = xbuf[(row0 + r) * RS + k];
            xvv[r] = pk2(xv, xv);
        }
        uint64_t wl2[CP2], wr2[CP2];
        if constexpr (CP2 == 2) {
            ulonglong2 a = *(const ulonglong2*)(Wl + k * FOUT + colbase);
            ulonglong2 b = *(const ulonglong2*)(Wr + k * FOUT + colbase);
            wl2[0] = a.x; wl2[1] = a.y; wr2[0] = b.x; wr2[1] = b.y;
        } else {
            wl2[0] = *(const uint64_t*)(Wl + k * FOUT + colbase);
            wr2[0] = *(const uint64_t*)(Wr + k * FOUT + colbase);
        }
#pragma unroll
        for (int r = 0; r < 4; r++)
#pragma unroll
            for (int c = 0; c < CP2; c++) {
                ffma2(accL[r][c], xvv[r], wl2[c], accL[r][c]);
                ffma2(accR[r][c], xvv[r], wr2[c], accR[r][c]);
            }
    }
#pragma unroll
    for (int r = 0; r < 4; r++) {
        if constexpr (CP2 == 2) {
            ulonglong2 sl; sl.x = accL[r][0]; sl.y = accL[r][1];
            ulonglong2 sr; sr.x = accR[r][0]; sr.y = accR[r][1];
            *(ulonglong2*)(xlbuf + (row0 + r) * RS + colbase) = sl;
            *(ulonglong2*)(xrbuf + (row0 + r) * RS + colbase) = sr;
        } else {
            *(uint64_t*)(xlbuf + (row0 + r) * RS + colbase) = accL[r][0];
            *(uint64_t*)(xrbuf + (row0 + r) * RS + colbase) = accR[r][0];
        }
    }
}

// ---------------------------------------------------------------------------
// dl[i,h] = sum_c xl[i,h,c]*att[h,c]; dr[j,h] = sum_c xr[j,h,c]*att[h,c]
// (linear part of leaky-relu decomposition lrelu(z) = 0.6 z + 0.4 |z|)
// ---------------------------------------------------------------------------
template <int HH, int CC>
__device__ void compute_dldr(const float* xlbuf, const float* xrbuf,
                             const float* __restrict__ att, float* DLp, float* DRp)
{
    const int t = threadIdx.x;
    if (t < 128 * HH) {
        const int which = (t >= 64 * HH) ? 1 : 0;
        const int idx = t - which * 64 * HH;
        const int h = idx % HH;
        const int i = idx / HH;
        const float* row = (which ? xrbuf : xlbuf) + i * RS + h * CC;
        const float* a = att + h * CC;
        float s0 = 0.f, s1 = 0.f, s2 = 0.f, s3 = 0.f;
#pragma unroll
        for (int c = 0; c < CC; c += 4) {
            float4 x = *(const float4*)(row + c);
            float4 av = *(const float4*)(a + c);
            s0 = fmaf(x.x, av.x, s0); s1 = fmaf(x.y, av.y, s1);
            s2 = fmaf(x.z, av.z, s2); s3 = fmaf(x.w, av.w, s3);
        }
        (which ? DRp : DLp)[idx] = (s0 + s1) + (s2 + s3);
    }
}

// ---------------------------------------------------------------------------
// e[h][i][j] = 0.6(dl_i + dr_j) + 0.4 sum_c |xl+xr| att, masked.
// Thread: j = t&63, rest = t>>6 -> (h, i-chunk). Packed inner loop.
// ---------------------------------------------------------------------------
template <int HH, int CC>
__device__ void compute_e(const float* xlbuf, const float* xrbuf,
                          const float* __restrict__ att,
                          const float* DLp, const float* DRp,
                          float* ebuf, const int* imp)
{
    const int t = threadIdx.x;
    const int j = t & 63;
    const int rest = t >> 6;
    const int h = rest % HH;
    const int ic = rest / HH;
    constexpr int ICNT = 8 * HH;       // i's per thread: 32 (L1/2) or 8 (L3)
    const int i0 = ic * ICNT;
    constexpr uint64_t ABSM = 0x7FFFFFFF7FFFFFFFULL;

    float eacc[ICNT];
#pragma unroll
    for (int ii = 0; ii < ICNT; ii++) eacc[ii] = 0.f;

#pragma unroll
    for (int ch = 0; ch < CC / 16; ch++) {
        uint64_t xr2[8], av2[8];
        {
            const ulonglong2* xp = (const ulonglong2*)(xrbuf + j * RS + h * CC + ch * 16);
            const ulonglong2* ap = (const ulonglong2*)(att + h * CC + ch * 16);
#pragma unroll
            for (int q = 0; q < 4; q++) {
                ulonglong2 xv = xp[q]; xr2[2*q] = xv.x; xr2[2*q+1] = xv.y;
                ulonglong2 av = ap[q]; av2[2*q] = av.x; av2[2*q+1] = av.y;
            }
        }
#pragma unroll
        for (int ii = 0; ii < ICNT; ii++) {
            const ulonglong2* xl2 = (const ulonglong2*)(xlbuf + (i0 + ii) * RS + h * CC + ch * 16);
            uint64_t s2 = 0ull;
#pragma unroll
            for (int q = 0; q < 4; q++) {
                ulonglong2 xv = xl2[q];
                uint64_t z0 = fadd2(xv.x, xr2[2*q])     & ABSM;
                uint64_t z1 = fadd2(xv.y, xr2[2*q + 1]) & ABSM;
                ffma2(s2, z0, av2[2*q], s2);
                ffma2(s2, z1, av2[2*q + 1], s2);
            }
            float2 s = upk2(s2);
            eacc[ii] += s.x + s.y;
        }
    }
    const int impj = imp[j];
    const float drv = DRp[j * HH + h];
#pragma unroll
    for (int ii = 0; ii < ICNT; ii++) {
        const int i = i0 + ii;
        float e = fmaf(0.4f, eacc[ii], 0.6f * (DLp[i * HH + h] + drv));
        bool ok = (i == j) || (impj && imp[i]);
        ebuf[h * EHS + i * 64 + j] = ok ? e : NEGV;
    }
}

// softmax over i for each (j,h), in place; e layout [h][i][j]
template <int HH>
__device__ void softmax_e(float* ebuf)
{
    const int t = threadIdx.x;
    if (t < 64 * HH) {
        const int j = t & 63;
        const int h = t >> 6;
        float* base = ebuf + h * EHS + j;
        float mx = -3.4e38f;
        for (int i = 0; i < 64; i++) mx = fmaxf(mx, base[i * 64]);
        float s = 0.f;
        for (int i = 0; i < 64; i++) {
            float ex = __expf(base[i * 64] - mx);
            base[i * 64] = ex;
            s += ex;
        }
        float inv = 1.f / s;
        for (int i = 0; i < 64; i++) base[i * 64] *= inv;
    }
}

// ---------------------------------------------------------------------------
// out[j][f] = sum_i alpha[h][i][j] * xl[i][f] + bias[f]
// Thread: f-slice of 4 floats x block of 4 j's -> each xl load feeds 16 FMAs.
// ---------------------------------------------------------------------------
template <int CC, int FOUT>
__device__ void aggregate(const float* xlbuf, const float* ebuf,
                          const float* __restrict__ bias, float* dst, int ds)
{
    const int t = threadIdx.x;
    constexpr int NFS = FOUT / 4;
    if (t < NFS * 16) {
        const int fs = t % NFS;
        const int jb = t / NFS;
        const int f0 = fs * 4;
        const int j0 = jb * 4;
        const int h = f0 / CC;
        uint64_t acc[4][2];
#pragma unroll
        for (int jj = 0; jj < 4; jj++) { acc[jj][0] = 0ull; acc[jj][1] = 0ull; }
#pragma unroll 4
        for (int i = 0; i < 64; i++) {
            float4 a4 = *(const float4*)(ebuf + h * EHS + i * 64 + j0);
            ulonglong2 xv = *(const ulonglong2*)(xlbuf + i * RS + f0);
            uint64_t a0 = pk2(a4.x, a4.x);
            uint64_t a1 = pk2(a4.y, a4.y);
            uint64_t a2 = pk2(a4.z, a4.z);
            uint64_t a3 = pk2(a4.w, a4.w);
            ffma2(acc[0][0], a0, xv.x, acc[0][0]); ffma2(acc[0][1], a0, xv.y, acc[0][1]);
            ffma2(acc[1][0], a1, xv.x, acc[1][0]); ffma2(acc[1][1], a1, xv.y, acc[1][1]);
            ffma2(acc[2][0], a2, xv.x, acc[2][0]); ffma2(acc[2][1], a2, xv.y, acc[2][1]);
            ffma2(acc[3][0], a3, xv.x, acc[3][0]); ffma2(acc[3][1], a3, xv.y, acc[3][1]);
        }
        float4 bv = *(const float4*)(bias + f0);
#pragma unroll
        for (int jj = 0; jj < 4; jj++) {
            float2 lo = upk2(acc[jj][0]);
            float2 hi = upk2(acc[jj][1]);
            float4 o;
            o.x = lo.x + bv.x; o.y = lo.y + bv.y;
            o.z = hi.x + bv.z; o.w = hi.y + bv.w;
            *(float4*)(dst + (j0 + jj) * ds + f0) = o;
        }
    }
}

// layernorm over 128 features + relu, in place. Warp per row, 4 rows per warp.
__device__ void ln_relu(float* xbuf, const float* __restrict__ g, const float* __restrict__ bb)
{
    const int w = threadIdx.x >> 5;
    const int lane = threadIdx.x & 31;
    for (int r = w; r < 64; r += 16) {
        float4 v = *(const float4*)(xbuf + r * RS + lane * 4);
        float sum = v.x + v.y + v.z + v.w;
        float sq  = v.x*v.x + v.y*v.y + v.z*v.z + v.w*v.w;
#pragma unroll
        for (int o = 16; o > 0; o >>= 1) {
            sum += __shfl_xor_sync(0xffffffffu, sum, o);
            sq  += __shfl_xor_sync(0xffffffffu, sq, o);
        }
        float mean = sum * (1.f / 128.f);
        float var  = sq * (1.f / 128.f) - mean * mean;
        float rstd = rsqrtf(var + 1e-5f);
        float4 gg = *(const float4*)(g + lane * 4);
        float4 bv = *(const float4*)(bb + lane * 4);
        float4 o;
        o.x = fmaxf((v.x - mean) * rstd * gg.x + bv.x, 0.f);
        o.y = fmaxf((v.y - mean) * rstd * gg.y + bv.y, 0.f);
        o.z = fmaxf((v.z - mean) * rstd * gg.z + bv.z, 0.f);
        o.w = fmaxf((v.w - mean) * rstd * gg.w + bv.w, 0.f);
        *(float4*)(xbuf + r * RS + lane * 4) = o;
    }
}

__global__ void __launch_bounds__(NT, 1)
GNN_61040075210810_kernel(
    const float* __restrict__ team_obs, const float* __restrict__ target_obs,
    const float* __restrict__ team_mask, const float* __restrict__ ltm,
    const float* __restrict__ W_emb, const float* __restrict__ b_emb,
    const float* __restrict__ Wl1, const float* __restrict__ Wr1,
    const float* __restrict__ att1, const float* __restrict__ b1,
    const float* __restrict__ Wl2, const float* __restrict__ Wr2,
    const float* __restrict__ att2, const float* __restrict__ b2,
    const float* __restrict__ Wl3, const float* __restrict__ Wr3,
    const float* __restrict__ att3, const float* __restrict__ b3,
    const float* __restrict__ ln1g, const float* __restrict__ ln1b,
    const float* __restrict__ ln2g, const float* __restrict__ ln2b,
    float* __restrict__ out)
{
    extern __shared__ float smf[];
    float* X  = smf + OFF_X;
    float* XL = smf + OFF_XL;
    float* XR = smf + OFF_XR;
    float* E  = smf + OFF_E;
    int*   IMP = (int*)(smf + OFF_IMP);
    float* DL = smf + OFF_DL;
    float* DR = smf + OFF_DR;

    const int b = blockIdx.x;
    const int t = threadIdx.x;

    // ---- feature assembly: fin (64 x 16) aliased into E ----
    float* FIN = E;
    for (int idx = t; idx < 1024; idx += NT) {
        int m = idx >> 4, k = idx & 15;
        float v;
        if (m < 16) {
            v = (k < 14) ? team_obs[(b * 16 + m) * 14 + k] : 0.f;
        } else {
            int tt = m - 16;
            if (k < 12)      v = target_obs[(b * 48 + tt) * 15 + k];
            else if (k < 14) v = 0.f;
            else             v = target_obs[(b * 48 + tt) * 15 + (k - 2)];
        }
        FIN[idx] = v;
    }
    if (t < 64) {
        bool ok = (t < 16) ? (team_mask[b * 32 + t] != NEGV)
                           : (ltm[b * 49 + (t - 16)] != 0.0f);
        IMP[t] = ok ? 1 : 0;
    }
    __syncthreads();

    // ---- embedding: X = FIN @ W_emb + b_emb  (64x16 @ 16x128) ----
    {
        const int w = t >> 5, lane = t & 31;
        const int row0 = w * 4;
        float acc[4][4];
#pragma unroll
        for (int r = 0; r < 4; r++)
#pragma unroll
            for (int c = 0; c < 4; c++) acc[r][c] = 0.f;
#pragma unroll
        for (int k = 0; k < 16; k++) {
            float xv[4];
#pragma unroll
            for (int r = 0; r < 4; r++) xv[r] = FIN[(row0 + r) * 16 + k];
            float4 wv = *(const float4*)(W_emb + k * 128 + lane * 4);
#pragma unroll
            for (int r = 0; r < 4; r++) {
                acc[r][0] = fmaf(xv[r], wv.x, acc[r][0]);
                acc[r][1] = fmaf(xv[r], wv.y, acc[r][1]);
                acc[r][2] = fmaf(xv[r], wv.z, acc[r][2]);
                acc[r][3] = fmaf(xv[r], wv.w, acc[r][3]);
            }
        }
        float4 be = *(const float4*)(b_emb + lane * 4);
#pragma unroll
        for (int r = 0; r < 4; r++) {
            float4 o;
            o.x = acc[r][0] + be.x; o.y = acc[r][1] + be.y;
            o.z = acc[r][2] + be.z; o.w = acc[r][3] + be.w;
            *(float4*)(X + (row0 + r) * RS + lane * 4) = o;
        }
    }
    __syncthreads();

    // ---- layer 1 ----
    dual_matmul<128>(Wl1, Wr1, X, XL, XR);
    __syncthreads();
    compute_dldr<4, 32>(XL, XR, att1, DL, DR);
    __syncthreads();
    compute_e<4, 32>(XL, XR, att1, DL, DR, E, IMP);
    __syncthreads();
    softmax_e<4>(E);
    __syncthreads();
    aggregate<32, 128>(XL, E, b1, X, RS);
    __syncthreads();
    ln_relu(X, ln1g, ln1b);
    __syncthreads();

    // ---- layer 2 ----
    dual_matmul<128>(Wl2, Wr2, X, XL, XR);
    __syncthreads();
    compute_dldr<4, 32>(XL, XR, att2, DL, DR);
    __syncthreads();
    compute_e<4, 32>(XL, XR, att2, DL, DR, E, IMP);
    __syncthreads();
    softmax_e<4>(E);
    __syncthreads();
    aggregate<32, 128>(XL, E, b2, X, RS);
    __syncthreads();
    ln_relu(X, ln2g, ln2b);
    __syncthreads();

    // ---- layer 3 (H=1, C=64) ----
    dual_matmul<64>(Wl3, Wr3, X, XL, XR);
    __syncthreads();
    compute_dldr<1, 64>(XL, XR, att3, DL, DR);
    __syncthreads();
    compute_e<1, 64>(XL, XR, att3, DL, DR, E, IMP);
    __syncthreads();
    softmax_e<1>(E);
    __syncthreads();
    aggregate<64, 64>(XL, E, b3, out + b * 64 * 64, 64);
}

extern "C" void kernel_launch(void* const* d_in, const int* in_sizes, int n_in,
                              void* d_out, int out_size)
{
    (void)in_sizes; (void)n_in; (void)out_size;
    cudaFuncSetAttribute(GNN_61040075210810_kernel,
                         cudaFuncAttributeMaxDynamicSharedMemorySize, SMEM_BYTES);
    GNN_61040075210810_kernel<<<128, NT, SMEM_BYTES>>>(
        (const float*)d_in[0],  (const float*)d_in[1],
        (const float*)d_in[2],  (const float*)d_in[3],
        (const float*)d_in[4],  (const float*)d_in[5],
        (const float*)d_in[6],  (const float*)d_in[7],
        (const float*)d_in[8],  (const float*)d_in[9],
        (const float*)d_in[10], (const float*)d_in[11],
        (const float*)d_in[12], (const float*)d_in[13],
        (const float*)d_in[14], (const float*)d_in[15],
        (const float*)d_in[16], (const float*)d_in[17],
        (const float*)d_in[18], (const float*)d_in[19],
        (const float*)d_in[20], (const float*)d_in[21],
        (float*)d_out);
}